// round 16
// baseline (speedup 1.0000x reference)
#include <cuda_runtime.h>
#include <cuda_fp16.h>
#include <cstdint>
#include <cstddef>

// Problem constants
#define Bg    16
#define Ntok  512
#define Eg    131072
#define MROWS (Bg * Ntok)          // 8192
#define NSEG  4
#define SEGROWS (MROWS / NSEG)     // 2048 rows = 4 batches per segment
#define SCALE 0.17677669529663687f // 1/sqrt(32)

// Scratch (device globals; no allocation allowed)
// g_mask zero at module load; attn re-zeros rows it reads -> replay-safe.
__device__ __align__(16) __half g_h16[MROWS * 256];
__device__ float    g_q[MROWS * 256];
__device__ __align__(16) __half g_k16[MROWS * 256];
__device__ __align__(16) __half g_v16[MROWS * 256];
__device__ __align__(16) __half g_att16[MROWS * 256];
__device__ unsigned g_mask[Bg * Ntok * 16];  // 131072 words
__device__ __align__(16) __half g_wt[4 * 256 * 256];

// Streams/events created once at program init (before harness checkpoints).
struct PipeRes {
    cudaStream_t s1, s2;
    cudaEvent_t  e0, eM, eQ[NSEG], eA[NSEG], eJ;
    PipeRes() {
        cudaStreamCreateWithFlags(&s1, cudaStreamNonBlocking);
        cudaStreamCreateWithFlags(&s2, cudaStreamNonBlocking);
        cudaEventCreateWithFlags(&e0, cudaEventDisableTiming);
        cudaEventCreateWithFlags(&eM, cudaEventDisableTiming);
        for (int i = 0; i < NSEG; i++) {
            cudaEventCreateWithFlags(&eQ[i], cudaEventDisableTiming);
            cudaEventCreateWithFlags(&eA[i], cudaEventDisableTiming);
        }
        cudaEventCreateWithFlags(&eJ, cudaEventDisableTiming);
    }
};
static PipeRes g_pipe;

// ---------------------------------------------------------------------------
// Warp-MMA helpers (portable sm_80+ path; harness PTX target is compute_100
// without 'a' suffix -> tcgen05 unavailable; mma.sync HMMA is the ceiling)
// ---------------------------------------------------------------------------
__device__ __forceinline__ void ldsm_x4(uint32_t addr, uint32_t* r) {
    asm volatile("ldmatrix.sync.aligned.m8n8.x4.shared.b16 {%0,%1,%2,%3}, [%4];"
                 : "=r"(r[0]), "=r"(r[1]), "=r"(r[2]), "=r"(r[3]) : "r"(addr));
}
__device__ __forceinline__ void ldsm_x2(uint32_t addr, uint32_t* r) {
    asm volatile("ldmatrix.sync.aligned.m8n8.x2.shared.b16 {%0,%1}, [%2];"
                 : "=r"(r[0]), "=r"(r[1]) : "r"(addr));
}
__device__ __forceinline__ void mma_f16(float* c, const uint32_t* a, const uint32_t* b) {
    asm volatile(
        "mma.sync.aligned.m16n8k16.row.col.f32.f16.f16.f32 "
        "{%0,%1,%2,%3}, {%4,%5,%6,%7}, {%8,%9}, {%0,%1,%2,%3};"
        : "+f"(c[0]), "+f"(c[1]), "+f"(c[2]), "+f"(c[3])
        : "r"(a[0]), "r"(a[1]), "r"(a[2]), "r"(a[3]), "r"(b[0]), "r"(b[1]));
}
__device__ __forceinline__ uint32_t pack_h2(__half a, __half b) {
    __half2 t(a, b);
    return *reinterpret_cast<uint32_t*>(&t);
}

// ---------------------------------------------------------------------------
// Fused prep: h fp32->fp16 (blocks 0..2047) + weight transpose/convert
// ---------------------------------------------------------------------------
__global__ void prep_kernel(const float* __restrict__ h,
                            const float* __restrict__ Wq, const float* __restrict__ Wk,
                            const float* __restrict__ Wv, const float* __restrict__ Wo,
                            __half* __restrict__ h16, __half* __restrict__ wt) {
    __shared__ float tile[32][33];
    int bx = blockIdx.x;
    int tid = threadIdx.x;
    if (bx < 2048) {
        int i = bx * 256 + tid;
        float4 v = reinterpret_cast<const float4*>(h)[i];
        uint2 u;
        u.x = pack_h2(__float2half_rn(v.x), __float2half_rn(v.y));
        u.y = pack_h2(__float2half_rn(v.z), __float2half_rn(v.w));
        reinterpret_cast<uint2*>(h16)[i] = u;
        return;
    }
    int wb   = bx - 2048;
    int wsel = wb >> 6;
    int blk  = wb & 63;
    const float* W = (wsel == 0) ? Wq : (wsel == 1) ? Wk
                   : (wsel == 2) ? Wv : Wo;
    int tx = tid & 31, ty = tid >> 5;
    int n0 = (blk & 7) * 32, k0 = (blk >> 3) * 32;
#pragma unroll
    for (int j = 0; j < 4; j++)
        tile[ty + 8 * j][tx] = W[(k0 + ty + 8 * j) * 256 + n0 + tx];
    __syncthreads();
    size_t wbase = (size_t)wsel * 65536;
#pragma unroll
    for (int j = 0; j < 4; j++) {
        int n = n0 + ty + 8 * j;
        int k = k0 + tx;
        wt[wbase + (size_t)n * 256 + k] = __float2half_rn(tile[tx][ty + 8 * j]);
    }
}

// ---------------------------------------------------------------------------
// Mask build (edges + self loops) onto the all-zero mask; attn re-zeros.
// ---------------------------------------------------------------------------
__global__ void mask_kernel(const int* __restrict__ src, const int* __restrict__ dst,
                            unsigned* __restrict__ mask) {
    int i = blockIdx.x * 256 + threadIdx.x;      // < Eg + MROWS
    if (i < Eg) {
        int s = src[i];
        int d = dst[i];
        int b = s >> 9;
        int r = s & 511;
        int c = d & 511;
        atomicOr(&mask[((b << 9) + r) * 16 + (c >> 5)], 1u << (c & 31));
    } else {
        int row = i - Eg;
        int qi = row & 511;
        atomicOr(&mask[row * 16 + (qi >> 5)], 1u << (qi & 31));
    }
}

// ---------------------------------------------------------------------------
// fp16 GEMM: C[128,64] per CTA = A[128,256]@Wt^T+bias. 256 thr, 8 warps,
// warp tile 32x32, double-buffered smem, one sync per chunk, 2 CTAs/SM.
// ---------------------------------------------------------------------------
#define KCH   32
#define NCHNK 8
#define ASTR  40

struct Pf {
    uint4 a[2];
    uint4 b;
};

__device__ __forceinline__ void pf_load(Pf& p, const __half* __restrict__ A,
                                        const __half* __restrict__ wt,
                                        int row0, int col0, int ch, int tid) {
#pragma unroll
    for (int i = 0; i < 2; i++) {
        int idx = tid + i * 256;
        int r = idx >> 2, c4 = idx & 3;
        p.a[i] = *reinterpret_cast<const uint4*>(
            A + (size_t)(row0 + r) * 256 + ch * KCH + c4 * 8);
    }
    int r = tid >> 2, q4 = tid & 3;
    p.b = *reinterpret_cast<const uint4*>(wt + (size_t)(col0 + r) * 256 + ch * KCH + q4 * 8);
}

__device__ __forceinline__ void pf_store(const Pf& p,
                                         __half* Ash, __half* Bsh, int tid) {
#pragma unroll
    for (int i = 0; i < 2; i++) {
        int idx = tid + i * 256;
        int r = idx >> 2, c4 = idx & 3;
        *reinterpret_cast<uint4*>(&Ash[r * ASTR + c4 * 8]) = p.a[i];
    }
    int r = tid >> 2, q4 = tid & 3;
    *reinterpret_cast<uint4*>(&Bsh[r * ASTR + q4 * 8]) = p.b;
}

__device__ __forceinline__ void mma_gemm_body(
    const __half* __restrict__ A,
    const __half* __restrict__ wt,
    const float* __restrict__ bias,
    float* __restrict__ C32, __half* __restrict__ C16,
    int row0, int col0) {
    __shared__ __align__(16) __half Ash[2][128 * ASTR];
    __shared__ __align__(16) __half Bsh[2][64 * ASTR];

    int tid  = threadIdx.x;
    int wid  = tid >> 5;
    int lane = tid & 31;
    int wrow = (wid >> 1) * 32;
    int wn   = (wid & 1) * 32;

    int arow = wrow + (lane & 15);
    int ac8  = ((lane >> 4) & 1) * 8;
    int brow = wn + (lane & 7);
    int bc8  = ((lane >> 3) & 1) * 8;

    float acc[2][4][4];
#pragma unroll
    for (int mt = 0; mt < 2; mt++)
#pragma unroll
        for (int nt = 0; nt < 4; nt++)
#pragma unroll
            for (int i = 0; i < 4; i++) acc[mt][nt][i] = 0.f;

    Pf pf;
    pf_load(pf, A, wt, row0, col0, 0, tid);
    pf_store(pf, Ash[0], Bsh[0], tid);
    __syncthreads();

#pragma unroll 1
    for (int ch = 0; ch < NCHNK; ch++) {
        if (ch + 1 < NCHNK)
            pf_load(pf, A, wt, row0, col0, ch + 1, tid);

        uint32_t a_b = (uint32_t)__cvta_generic_to_shared(Ash[ch & 1]);
        uint32_t b_b = (uint32_t)__cvta_generic_to_shared(Bsh[ch & 1]);
#pragma unroll
        for (int ks = 0; ks < 2; ks++) {
            uint32_t ah[2][4], bh[4][2];
#pragma unroll
            for (int mt = 0; mt < 2; mt++) {
                uint32_t off = (uint32_t)(((arow + mt * 16) * ASTR + ks * 16 + ac8) * 2);
                ldsm_x4(a_b + off, ah[mt]);
            }
#pragma unroll
            for (int nt = 0; nt < 4; nt++) {
                uint32_t off = (uint32_t)(((brow + nt * 8) * ASTR + ks * 16 + bc8) * 2);
                ldsm_x2(b_b + off, bh[nt]);
            }
#pragma unroll
            for (int mt = 0; mt < 2; mt++)
#pragma unroll
                for (int nt = 0; nt < 4; nt++)
                    mma_f16(acc[mt][nt], ah[mt], bh[nt]);
        }
        if (ch + 1 < NCHNK) {
            pf_store(pf, Ash[(ch + 1) & 1], Bsh[(ch + 1) & 1], tid);
            __syncthreads();
        }
    }

#pragma unroll
    for (int mt = 0; mt < 2; mt++) {
#pragma unroll
        for (int nt = 0; nt < 4; nt++) {
            int r = row0 + wrow + mt * 16 + (lane >> 2);
            int c = col0 + wn + nt * 8 + (lane & 3) * 2;
            float b0 = bias[c], b1 = bias[c + 1];
            float v00 = acc[mt][nt][0] + b0, v01 = acc[mt][nt][1] + b1;
            float v10 = acc[mt][nt][2] + b0, v11 = acc[mt][nt][3] + b1;
            if (C16) {
                *reinterpret_cast<uint32_t*>(C16 + (size_t)r * 256 + c) =
                    pack_h2(__float2half_rn(v00), __float2half_rn(v01));
                *reinterpret_cast<uint32_t*>(C16 + (size_t)(r + 8) * 256 + c) =
                    pack_h2(__float2half_rn(v10), __float2half_rn(v11));
            } else {
                *reinterpret_cast<float2*>(C32 + (size_t)r * 256 + c) =
                    make_float2(v00, v01);
                *reinterpret_cast<float2*>(C32 + (size_t)(r + 8) * 256 + c) =
                    make_float2(v10, v11);
            }
        }
    }
}

__global__ __launch_bounds__(256, 2) void mma_qkv_kernel(
    const __half* __restrict__ A, const __half* __restrict__ wt,
    const float* bq, const float* bk, const float* bv,
    float* q, __half* k16, __half* v16, int rowbase) {
    int wsel = blockIdx.z;
    const float* bias = (wsel == 0) ? bq : (wsel == 1) ? bk : bv;
    float* C32 = (wsel == 0) ? q : nullptr;
    __half* C16 = (wsel == 1) ? k16 : (wsel == 2) ? v16 : nullptr;
    mma_gemm_body(A, wt + (size_t)wsel * 65536, bias, C32, C16,
                  rowbase + blockIdx.x * 128, blockIdx.y * 64);
}

__global__ __launch_bounds__(256, 2) void mma_o_kernel(
    const __half* __restrict__ A, const __half* __restrict__ wt,
    const float* __restrict__ bias, float* __restrict__ C, int rowbase) {
    mma_gemm_body(A, wt + (size_t)3 * 65536, bias, C, nullptr,
                  rowbase + blockIdx.x * 128, blockIdx.y * 64);
}

// ---------------------------------------------------------------------------
// Sparse masked attention (k/v fp16, fp16 output). Warp per (b,q), 8 heads.
// Zeroes its mask rows after use (replay-safe).
// ---------------------------------------------------------------------------
__global__ __launch_bounds__(256) void attn_kernel(
    const float* __restrict__ q, const __half* __restrict__ k,
    const __half* __restrict__ v, unsigned* __restrict__ mask,
    __half* __restrict__ att16, int rowbase) {
    int gw   = rowbase + blockIdx.x * 8 + (threadIdx.x >> 5);
    int lane = threadIdx.x & 31;
    int qi = gw & 511;
    int b  = gw >> 9;

    int off = lane * 8;
    size_t qrow = (size_t)gw * 256;
    float4 qa = *reinterpret_cast<const float4*>(q + qrow + off);
    float4 qb = *reinterpret_cast<const float4*>(q + qrow + off + 4);

    float m = -1e30f, l = 0.f;
    float acc[8];
#pragma unroll
    for (int d = 0; d < 8; d++) acc[d] = 0.f;

    unsigned* mrow = mask + ((b << 9) + qi) * 16;
    size_t bbase = (size_t)(b << 9) * 256;

#pragma unroll 1
    for (int w = 0; w < 16; w++) {
        unsigned bits = mrow[w];
        while (bits) {
            int bit = __ffs(bits) - 1;
            bits &= bits - 1;
            int j = (w << 5) + bit;
            size_t rbase = bbase + (size_t)j * 256 + off;
            uint4 ku = *reinterpret_cast<const uint4*>(k + rbase);
            uint4 vu = *reinterpret_cast<const uint4*>(v + rbase);
            const __half2* kh = reinterpret_cast<const __half2*>(&ku);
            const __half2* vh = reinterpret_cast<const __half2*>(&vu);
            float2 k0 = __half22float2(kh[0]);
            float2 k1 = __half22float2(kh[1]);
            float2 k2 = __half22float2(kh[2]);
            float2 k3 = __half22float2(kh[3]);

            float s = qa.x * k0.x + qa.y * k0.y + qa.z * k1.x + qa.w * k1.y
                    + qb.x * k2.x + qb.y * k2.y + qb.z * k3.x + qb.w * k3.y;
            s += __shfl_xor_sync(0xffffffffu, s, 1);
            s += __shfl_xor_sync(0xffffffffu, s, 2);
            s *= SCALE;

            float mn   = fmaxf(m, s);
            float corr = __expf(m - mn);
            float p    = __expf(s - mn);
            l = l * corr + p;
            m = mn;
            float2 v0 = __half22float2(vh[0]);
            float2 v1 = __half22float2(vh[1]);
            float2 v2 = __half22float2(vh[2]);
            float2 v3 = __half22float2(vh[3]);
            acc[0] = acc[0] * corr + p * v0.x;
            acc[1] = acc[1] * corr + p * v0.y;
            acc[2] = acc[2] * corr + p * v1.x;
            acc[3] = acc[3] * corr + p * v1.y;
            acc[4] = acc[4] * corr + p * v2.x;
            acc[5] = acc[5] * corr + p * v2.y;
            acc[6] = acc[6] * corr + p * v3.x;
            acc[7] = acc[7] * corr + p * v3.y;
        }
    }

    if (lane < 16) mrow[lane] = 0u;   // restore all-zero invariant

    float inv = 1.f / l;
    uint4 u;
    u.x = pack_h2(__float2half_rn(acc[0] * inv), __float2half_rn(acc[1] * inv));
    u.y = pack_h2(__float2half_rn(acc[2] * inv), __float2half_rn(acc[3] * inv));
    u.z = pack_h2(__float2half_rn(acc[4] * inv), __float2half_rn(acc[5] * inv));
    u.w = pack_h2(__float2half_rn(acc[6] * inv), __float2half_rn(acc[7] * inv));
    *reinterpret_cast<uint4*>(att16 + qrow + off) = u;
}

// ---------------------------------------------------------------------------
// Launch: 4-segment software pipeline over 3 streams.
//   S (default): prep -> qkv(0..3)        [eQ[s] after each]
//   s1: mask [eM] -> O(s) after eA[s]     [eJ at end]
//   s2: attn(s) after eM + eQ[s]          [eA[s] after each]
// ---------------------------------------------------------------------------
extern "C" void kernel_launch(void* const* d_in, const int* in_sizes, int n_in,
                              void* d_out, int out_size) {
    const float* h   = (const float*)d_in[0];
    const int*   src = (const int*)d_in[1];
    const int*   dst = (const int*)d_in[2];
    const float* Wq  = (const float*)d_in[3];
    const float* bq  = (const float*)d_in[4];
    const float* Wk  = (const float*)d_in[5];
    const float* bk  = (const float*)d_in[6];
    const float* Wv  = (const float*)d_in[7];
    const float* bv  = (const float*)d_in[8];
    const float* Wo  = (const float*)d_in[9];
    const float* bo  = (const float*)d_in[10];
    float* out = (float*)d_out;

    float *pq;
    __half *ph16, *pk16, *pv16, *patt16, *pwt;
    unsigned* pmask;
    cudaGetSymbolAddress((void**)&ph16,   g_h16);
    cudaGetSymbolAddress((void**)&pq,     g_q);
    cudaGetSymbolAddress((void**)&pk16,   g_k16);
    cudaGetSymbolAddress((void**)&pv16,   g_v16);
    cudaGetSymbolAddress((void**)&patt16, g_att16);
    cudaGetSymbolAddress((void**)&pmask,  g_mask);
    cudaGetSymbolAddress((void**)&pwt,    g_wt);

    cudaStream_t S = 0;
    PipeRes& P = g_pipe;

    // Fork point
    cudaEventRecord(P.e0, S);

    // s1: mask build (independent of prep)
    cudaStreamWaitEvent(P.s1, P.e0, 0);
    mask_kernel<<<(Eg + MROWS) / 256, 256, 0, P.s1>>>(src, dst, pmask);
    cudaEventRecord(P.eM, P.s1);

    // S: prep, then qkv segments
    prep_kernel<<<2304, 256, 0, S>>>(h, Wq, Wk, Wv, Wo, ph16, pwt);
    for (int s = 0; s < NSEG; s++) {
        mma_qkv_kernel<<<dim3(SEGROWS / 128, 4, 3), 256, 0, S>>>(
            ph16, pwt, bq, bk, bv, pq, pk16, pv16, s * SEGROWS);
        cudaEventRecord(P.eQ[s], S);
    }

    // s2: attn segments (need mask + their qkv segment)
    cudaStreamWaitEvent(P.s2, P.eM, 0);
    for (int s = 0; s < NSEG; s++) {
        cudaStreamWaitEvent(P.s2, P.eQ[s], 0);
        attn_kernel<<<SEGROWS / 8, 256, 0, P.s2>>>(
            pq, pk16, pv16, pmask, patt16, s * SEGROWS);
        cudaEventRecord(P.eA[s], P.s2);
    }

    // s1: O segments (need their attn segment; wt via transitive deps)
    for (int s = 0; s < NSEG; s++) {
        cudaStreamWaitEvent(P.s1, P.eA[s], 0);
        mma_o_kernel<<<dim3(SEGROWS / 128, 4), 256, 0, P.s1>>>(
            patt16, pwt, bo, out, s * SEGROWS);
    }
    cudaEventRecord(P.eJ, P.s1);

    // Join everything back into S
    cudaStreamWaitEvent(S, P.eJ, 0);
    cudaStreamWaitEvent(S, P.eA[NSEG - 1], 0);
}

// round 17
// speedup vs baseline: 1.3783x; 1.3783x over previous
#include <cuda_runtime.h>
#include <cuda_fp16.h>
#include <cstdint>
#include <cstddef>

// Problem constants
#define Bg    16
#define Ntok  512
#define Eg    131072
#define MROWS (Bg * Ntok)          // 8192
#define SCALE 0.17677669529663687f // 1/sqrt(32)

// Scratch (device globals; no allocation allowed)
// g_mask zero at module load; attn re-zeros rows it reads -> replay-safe.
__device__ __align__(16) __half g_h16[MROWS * 256];
__device__ float    g_q[MROWS * 256];
__device__ __align__(16) __half g_k16[MROWS * 256];
__device__ __align__(16) __half g_v16[MROWS * 256];
__device__ __align__(16) __half g_att16[MROWS * 256];
__device__ unsigned g_mask[Bg * Ntok * 16];  // 131072 words
__device__ __align__(16) __half g_wt[4 * 256 * 256];

// ---------------------------------------------------------------------------
// Warp-MMA helpers (portable sm_80+ path; harness PTX target is compute_100
// without 'a' suffix -> tcgen05 unavailable; mma.sync HMMA is the ceiling)
// ---------------------------------------------------------------------------
__device__ __forceinline__ void ldsm_x4(uint32_t addr, uint32_t* r) {
    asm volatile("ldmatrix.sync.aligned.m8n8.x4.shared.b16 {%0,%1,%2,%3}, [%4];"
                 : "=r"(r[0]), "=r"(r[1]), "=r"(r[2]), "=r"(r[3]) : "r"(addr));
}
__device__ __forceinline__ void ldsm_x2(uint32_t addr, uint32_t* r) {
    asm volatile("ldmatrix.sync.aligned.m8n8.x2.shared.b16 {%0,%1}, [%2];"
                 : "=r"(r[0]), "=r"(r[1]) : "r"(addr));
}
__device__ __forceinline__ void mma_f16(float* c, const uint32_t* a, const uint32_t* b) {
    asm volatile(
        "mma.sync.aligned.m16n8k16.row.col.f32.f16.f16.f32 "
        "{%0,%1,%2,%3}, {%4,%5,%6,%7}, {%8,%9}, {%0,%1,%2,%3};"
        : "+f"(c[0]), "+f"(c[1]), "+f"(c[2]), "+f"(c[3])
        : "r"(a[0]), "r"(a[1]), "r"(a[2]), "r"(a[3]), "r"(b[0]), "r"(b[1]));
}
__device__ __forceinline__ uint32_t pack_h2(__half a, __half b) {
    __half2 t(a, b);
    return *reinterpret_cast<uint32_t*>(&t);
}

// ---------------------------------------------------------------------------
// Fused prep: h fp32->fp16 (blocks 0..2047) + weight transpose/convert
// ---------------------------------------------------------------------------
__global__ void prep_kernel(const float* __restrict__ h,
                            const float* __restrict__ Wq, const float* __restrict__ Wk,
                            const float* __restrict__ Wv, const float* __restrict__ Wo,
                            __half* __restrict__ h16, __half* __restrict__ wt) {
    __shared__ float tile[32][33];
    int bx = blockIdx.x;
    int tid = threadIdx.x;
    if (bx < 2048) {
        int i = bx * 256 + tid;
        float4 v = reinterpret_cast<const float4*>(h)[i];
        uint2 u;
        u.x = pack_h2(__float2half_rn(v.x), __float2half_rn(v.y));
        u.y = pack_h2(__float2half_rn(v.z), __float2half_rn(v.w));
        reinterpret_cast<uint2*>(h16)[i] = u;
        return;
    }
    int wb   = bx - 2048;
    int wsel = wb >> 6;
    int blk  = wb & 63;
    const float* W = (wsel == 0) ? Wq : (wsel == 1) ? Wk
                   : (wsel == 2) ? Wv : Wo;
    int tx = tid & 31, ty = tid >> 5;
    int n0 = (blk & 7) * 32, k0 = (blk >> 3) * 32;
#pragma unroll
    for (int j = 0; j < 4; j++)
        tile[ty + 8 * j][tx] = W[(k0 + ty + 8 * j) * 256 + n0 + tx];
    __syncthreads();
    size_t wbase = (size_t)wsel * 65536;
#pragma unroll
    for (int j = 0; j < 4; j++) {
        int n = n0 + ty + 8 * j;
        int k = k0 + tx;
        wt[wbase + (size_t)n * 256 + k] = __float2half_rn(tile[tx][ty + 8 * j]);
    }
}

// ---------------------------------------------------------------------------
// fp16 GEMM: C[128,64] per CTA = A[128,256]@Wt^T+bias. 256 thr, 8 warps,
// warp tile 32x32, double-buffered smem, one sync per chunk, 2 CTAs/SM.
// ---------------------------------------------------------------------------
#define KCH   32
#define NCHNK 8
#define ASTR  40

struct Pf {
    uint4 a[2];
    uint4 b;
};

__device__ __forceinline__ void pf_load(Pf& p, const __half* __restrict__ A,
                                        const __half* __restrict__ wt,
                                        int row0, int col0, int ch, int tid) {
#pragma unroll
    for (int i = 0; i < 2; i++) {
        int idx = tid + i * 256;
        int r = idx >> 2, c4 = idx & 3;
        p.a[i] = *reinterpret_cast<const uint4*>(
            A + (size_t)(row0 + r) * 256 + ch * KCH + c4 * 8);
    }
    int r = tid >> 2, q4 = tid & 3;
    p.b = *reinterpret_cast<const uint4*>(wt + (size_t)(col0 + r) * 256 + ch * KCH + q4 * 8);
}

__device__ __forceinline__ void pf_store(const Pf& p,
                                         __half* Ash, __half* Bsh, int tid) {
#pragma unroll
    for (int i = 0; i < 2; i++) {
        int idx = tid + i * 256;
        int r = idx >> 2, c4 = idx & 3;
        *reinterpret_cast<uint4*>(&Ash[r * ASTR + c4 * 8]) = p.a[i];
    }
    int r = tid >> 2, q4 = tid & 3;
    *reinterpret_cast<uint4*>(&Bsh[r * ASTR + q4 * 8]) = p.b;
}

__device__ __forceinline__ void mma_gemm_body(
    const __half* __restrict__ A,
    const __half* __restrict__ wt,
    const float* __restrict__ bias,
    float* __restrict__ C32, __half* __restrict__ C16,
    int row0, int col0) {
    __shared__ __align__(16) __half Ash[2][128 * ASTR];
    __shared__ __align__(16) __half Bsh[2][64 * ASTR];

    int tid  = threadIdx.x;
    int wid  = tid >> 5;
    int lane = tid & 31;
    int wrow = (wid >> 1) * 32;
    int wn   = (wid & 1) * 32;

    int arow = wrow + (lane & 15);
    int ac8  = ((lane >> 4) & 1) * 8;
    int brow = wn + (lane & 7);
    int bc8  = ((lane >> 3) & 1) * 8;

    float acc[2][4][4];
#pragma unroll
    for (int mt = 0; mt < 2; mt++)
#pragma unroll
        for (int nt = 0; nt < 4; nt++)
#pragma unroll
            for (int i = 0; i < 4; i++) acc[mt][nt][i] = 0.f;

    Pf pf;
    pf_load(pf, A, wt, row0, col0, 0, tid);
    pf_store(pf, Ash[0], Bsh[0], tid);
    __syncthreads();

#pragma unroll 1
    for (int ch = 0; ch < NCHNK; ch++) {
        if (ch + 1 < NCHNK)
            pf_load(pf, A, wt, row0, col0, ch + 1, tid);

        uint32_t a_b = (uint32_t)__cvta_generic_to_shared(Ash[ch & 1]);
        uint32_t b_b = (uint32_t)__cvta_generic_to_shared(Bsh[ch & 1]);
#pragma unroll
        for (int ks = 0; ks < 2; ks++) {
            uint32_t ah[2][4], bh[4][2];
#pragma unroll
            for (int mt = 0; mt < 2; mt++) {
                uint32_t off = (uint32_t)(((arow + mt * 16) * ASTR + ks * 16 + ac8) * 2);
                ldsm_x4(a_b + off, ah[mt]);
            }
#pragma unroll
            for (int nt = 0; nt < 4; nt++) {
                uint32_t off = (uint32_t)(((brow + nt * 8) * ASTR + ks * 16 + bc8) * 2);
                ldsm_x2(b_b + off, bh[nt]);
            }
#pragma unroll
            for (int mt = 0; mt < 2; mt++)
#pragma unroll
                for (int nt = 0; nt < 4; nt++)
                    mma_f16(acc[mt][nt], ah[mt], bh[nt]);
        }
        if (ch + 1 < NCHNK) {
            pf_store(pf, Ash[(ch + 1) & 1], Bsh[(ch + 1) & 1], tid);
            __syncthreads();
        }
    }

#pragma unroll
    for (int mt = 0; mt < 2; mt++) {
#pragma unroll
        for (int nt = 0; nt < 4; nt++) {
            int r = row0 + wrow + mt * 16 + (lane >> 2);
            int c = col0 + wn + nt * 8 + (lane & 3) * 2;
            float b0 = bias[c], b1 = bias[c + 1];
            float v00 = acc[mt][nt][0] + b0, v01 = acc[mt][nt][1] + b1;
            float v10 = acc[mt][nt][2] + b0, v11 = acc[mt][nt][3] + b1;
            if (C16) {
                *reinterpret_cast<uint32_t*>(C16 + (size_t)r * 256 + c) =
                    pack_h2(__float2half_rn(v00), __float2half_rn(v01));
                *reinterpret_cast<uint32_t*>(C16 + (size_t)(r + 8) * 256 + c) =
                    pack_h2(__float2half_rn(v10), __float2half_rn(v11));
            } else {
                *reinterpret_cast<float2*>(C32 + (size_t)r * 256 + c) =
                    make_float2(v00, v01);
                *reinterpret_cast<float2*>(C32 + (size_t)(r + 8) * 256 + c) =
                    make_float2(v10, v11);
            }
        }
    }
}

// QKV GEMM with fused mask build (R15 config: full 8192-row grid, 768 CTAs).
__global__ __launch_bounds__(256, 2) void mma_qkv_kernel(
    const __half* __restrict__ A, const __half* __restrict__ wt,
    const float* bq, const float* bk, const float* bv,
    float* q, __half* k16, __half* v16,
    const int* __restrict__ src, const int* __restrict__ dst,
    unsigned* __restrict__ mask) {
    // --- fused mask build (atomics hide in GEMM issue slack) ---
    int gid = ((blockIdx.z * gridDim.y + blockIdx.y) * gridDim.x + blockIdx.x) * 256
              + threadIdx.x;                       // 0..196607
    if (gid < Eg) {
        int s = src[gid];
        int d = dst[gid];
        int b = s >> 9;
        int r = s & 511;
        int c = d & 511;
        atomicOr(&mask[((b << 9) + r) * 16 + (c >> 5)], 1u << (c & 31));
    } else if (gid < Eg + MROWS) {
        int row = gid - Eg;
        int qi = row & 511;
        atomicOr(&mask[row * 16 + (qi >> 5)], 1u << (qi & 31));
    }

    // --- GEMM ---
    int wsel = blockIdx.z;
    const float* bias = (wsel == 0) ? bq : (wsel == 1) ? bk : bv;
    float* C32 = (wsel == 0) ? q : nullptr;
    __half* C16 = (wsel == 1) ? k16 : (wsel == 2) ? v16 : nullptr;
    mma_gemm_body(A, wt + (size_t)wsel * 65536, bias, C32, C16,
                  blockIdx.x * 128, blockIdx.y * 64);
}

__global__ __launch_bounds__(256, 2) void mma_o_kernel(
    const __half* __restrict__ A, const __half* __restrict__ wt,
    const float* __restrict__ bias, float* __restrict__ C) {
    mma_gemm_body(A, wt + (size_t)3 * 65536, bias, C, nullptr,
                  blockIdx.x * 128, blockIdx.y * 64);
}

// ---------------------------------------------------------------------------
// Sparse masked attention with 1-edge LOOKAHEAD: the next edge's k/v loads
// are issued before the current edge's softmax update (loads depend only on
// the mask scan, not on softmax state) -> MLP=2, hides ~half the L2 latency.
// Same edges, same order, same fp32 math as R15. Warp per (b,q), 8 heads.
// Zeroes its mask rows after use (replay-safe).
// ---------------------------------------------------------------------------
__global__ __launch_bounds__(256) void attn_kernel(
    const float* __restrict__ q, const __half* __restrict__ k,
    const __half* __restrict__ v, unsigned* __restrict__ mask,
    __half* __restrict__ att16) {
    int gw   = blockIdx.x * 8 + (threadIdx.x >> 5);
    int lane = threadIdx.x & 31;
    int qi = gw & 511;
    int b  = gw >> 9;

    int off = lane * 8;
    size_t qrow = (size_t)gw * 256;
    float4 qa = *reinterpret_cast<const float4*>(q + qrow + off);
    float4 qb = *reinterpret_cast<const float4*>(q + qrow + off + 4);

    float m = -1e30f, l = 0.f;
    float acc[8];
#pragma unroll
    for (int d = 0; d < 8; d++) acc[d] = 0.f;

    unsigned* mrow = mask + ((b << 9) + qi) * 16;
    size_t bbase = (size_t)(b << 9) * 256;

    // --- scan state (every row has >=1 edge: the self loop) ---
    int w = 0;
    unsigned bits = mrow[0];
    while (bits == 0 && w < 15) bits = mrow[++w];

    int j = (w << 5) + __ffs(bits) - 1;
    bits &= bits - 1;
    size_t rbase = bbase + (size_t)j * 256 + off;
    uint4 ku = *reinterpret_cast<const uint4*>(k + rbase);
    uint4 vu = *reinterpret_cast<const uint4*>(v + rbase);

#pragma unroll 1
    for (;;) {
        // advance scan to next edge and issue its loads BEFORE processing
        while (bits == 0 && w < 15) bits = mrow[++w];
        bool more = (bits != 0);
        uint4 kun, vun;
        if (more) {
            int jn = (w << 5) + __ffs(bits) - 1;
            bits &= bits - 1;
            size_t rn = bbase + (size_t)jn * 256 + off;
            kun = *reinterpret_cast<const uint4*>(k + rn);
            vun = *reinterpret_cast<const uint4*>(v + rn);
        }

        // process current edge
        const __half2* kh = reinterpret_cast<const __half2*>(&ku);
        const __half2* vh = reinterpret_cast<const __half2*>(&vu);
        float2 k0 = __half22float2(kh[0]);
        float2 k1 = __half22float2(kh[1]);
        float2 k2 = __half22float2(kh[2]);
        float2 k3 = __half22float2(kh[3]);

        float s = qa.x * k0.x + qa.y * k0.y + qa.z * k1.x + qa.w * k1.y
                + qb.x * k2.x + qb.y * k2.y + qb.z * k3.x + qb.w * k3.y;
        s += __shfl_xor_sync(0xffffffffu, s, 1);
        s += __shfl_xor_sync(0xffffffffu, s, 2);
        s *= SCALE;

        float mn   = fmaxf(m, s);
        float corr = __expf(m - mn);
        float p    = __expf(s - mn);
        l = l * corr + p;
        m = mn;
        float2 v0 = __half22float2(vh[0]);
        float2 v1 = __half22float2(vh[1]);
        float2 v2 = __half22float2(vh[2]);
        float2 v3 = __half22float2(vh[3]);
        acc[0] = acc[0] * corr + p * v0.x;
        acc[1] = acc[1] * corr + p * v0.y;
        acc[2] = acc[2] * corr + p * v1.x;
        acc[3] = acc[3] * corr + p * v1.y;
        acc[4] = acc[4] * corr + p * v2.x;
        acc[5] = acc[5] * corr + p * v2.y;
        acc[6] = acc[6] * corr + p * v3.x;
        acc[7] = acc[7] * corr + p * v3.y;

        if (!more) break;
        ku = kun;
        vu = vun;
    }

    if (lane < 16) mrow[lane] = 0u;   // restore all-zero invariant

    float inv = 1.f / l;
    uint4 u;
    u.x = pack_h2(__float2half_rn(acc[0] * inv), __float2half_rn(acc[1] * inv));
    u.y = pack_h2(__float2half_rn(acc[2] * inv), __float2half_rn(acc[3] * inv));
    u.z = pack_h2(__float2half_rn(acc[4] * inv), __float2half_rn(acc[5] * inv));
    u.w = pack_h2(__float2half_rn(acc[6] * inv), __float2half_rn(acc[7] * inv));
    *reinterpret_cast<uint4*>(att16 + qrow + off) = u;
}

// ---------------------------------------------------------------------------
// Launch (4 kernels, single stream -- R15 structure)
// ---------------------------------------------------------------------------
extern "C" void kernel_launch(void* const* d_in, const int* in_sizes, int n_in,
                              void* d_out, int out_size) {
    const float* h   = (const float*)d_in[0];
    const int*   src = (const int*)d_in[1];
    const int*   dst = (const int*)d_in[2];
    const float* Wq  = (const float*)d_in[3];
    const float* bq  = (const float*)d_in[4];
    const float* Wk  = (const float*)d_in[5];
    const float* bk  = (const float*)d_in[6];
    const float* Wv  = (const float*)d_in[7];
    const float* bv  = (const float*)d_in[8];
    const float* Wo  = (const float*)d_in[9];
    const float* bo  = (const float*)d_in[10];
    float* out = (float*)d_out;

    float *pq;
    __half *ph16, *pk16, *pv16, *patt16, *pwt;
    unsigned* pmask;
    cudaGetSymbolAddress((void**)&ph16,   g_h16);
    cudaGetSymbolAddress((void**)&pq,     g_q);
    cudaGetSymbolAddress((void**)&pk16,   g_k16);
    cudaGetSymbolAddress((void**)&pv16,   g_v16);
    cudaGetSymbolAddress((void**)&patt16, g_att16);
    cudaGetSymbolAddress((void**)&pmask,  g_mask);
    cudaGetSymbolAddress((void**)&pwt,    g_wt);

    // Prep: h fp16 + weight transpose/convert (one launch)
    prep_kernel<<<2304, 256>>>(h, Wq, Wk, Wv, Wo, ph16, pwt);

    // Q/K/V projections with fused mask build
    mma_qkv_kernel<<<dim3(MROWS / 128, 4, 3), 256>>>(
        ph16, pwt, bq, bk, bv, pq, pk16, pv16, src, dst, pmask);

    // Sparse masked attention -> fp16 output; restores mask to zero
    attn_kernel<<<MROWS / 8, 256>>>(pq, pk16, pv16, pmask, patt16);

    // Output projection straight into d_out
    mma_o_kernel<<<dim3(MROWS / 128, 4), 256>>>(patt16, pwt, bo, out);
}